// round 3
// baseline (speedup 1.0000x reference)
#include <cuda_runtime.h>

// Problem constants
#define S    8
#define NCH  7
#define PIX  409600           // 640*640
#define LAMBDA 0.7f
#define EPSV 1e-6f
#define NBIN 1024             // 10-bit radix digits; key is 30 bits (value in [0,0.5))

// ---------------- device scratch (zero at module load; reduce's last block
// restores the zero invariant each replay) --------------------------------
__device__ float    g_predn[S * PIX];
__device__ int      g_npos[S];
__device__ __align__(16) unsigned g_histA[S][NBIN];   // pass 0 (key>>20)
__device__ __align__(16) unsigned g_histB[S][NBIN];   // pass 1 ((key>>10)&1023)
__device__ __align__(16) unsigned g_histC[S][NBIN];   // pass 2 (key&1023)
__device__ unsigned g_d0[S], g_krem0[S];              // after pass-0 pick
__device__ unsigned g_pref1[S], g_krem1[S];           // after pass-1 pick
__device__ float    g_acc[S][21];
__device__ unsigned g_counter;

__device__ __forceinline__ float sigmoidf(float x) {
    return 1.f / (1.f + __expf(-x));
}

__device__ __forceinline__ bool ohem_active(int s, unsigned& k) {
    int np = g_npos[s];
    k = (unsigned)(np * 3);
    return ((unsigned)(PIX - np) > k) && (k > 0);
}

// Warp-dedup'd shared histogram add: one atomic per distinct bin per warp.
__device__ __forceinline__ void hist_add(unsigned* sh, bool participate, unsigned bin) {
    unsigned ballot = __ballot_sync(0xffffffffu, participate);
    if (participate) {
        unsigned grp = __match_any_sync(ballot, bin);
        int leader = __ffs(grp) - 1;
        if ((int)(threadIdx.x & 31) == leader)
            atomicAdd(&sh[bin], (unsigned)__popc(grp));
    }
}

// Radix digit pick over a 1024-bin histogram row, 256 threads, 2 barriers.
// Finds d = max bin with suffix_sum(d) >= krem; newkrem = krem - suffix_sum(d+1).
__device__ __forceinline__ void radix_pick(const unsigned* __restrict__ hrow,
                                           unsigned krem,
                                           unsigned* shbuf,     // >= 10 words
                                           unsigned& digit, unsigned& newkrem) {
    int tid = threadIdx.x, lane = tid & 31, w = tid >> 5;
    uint4 h = ((const uint4*)hrow)[tid];           // bins 4t .. 4t+3
    unsigned local = h.x + h.y + h.z + h.w;
    unsigned v = local;                            // warp inclusive suffix sum
    #pragma unroll
    for (int o = 1; o < 32; o <<= 1) {
        unsigned u = __shfl_down_sync(0xffffffffu, v, o);
        if (lane + o < 32) v += u;
    }
    if (lane == 0) shbuf[w] = v;                   // warp totals
    __syncthreads();
    unsigned after_w = 0;
    #pragma unroll
    for (int j = 0; j < 8; j++) if (j > w) after_w += shbuf[j];
    unsigned suf_me    = v + after_w;              // sum of bins >= 4t
    unsigned suf_after = suf_me - local;           // sum of bins >= 4t+4
    unsigned s3 = h.w + suf_after;
    unsigned s2 = h.z + s3;
    unsigned s1 = h.y + s2;
    unsigned s0 = h.x + s1;
    if (s0 >= krem && s1 < krem)        { shbuf[8] = 4u*tid + 0u; shbuf[9] = krem - s1; }
    if (s1 >= krem && s2 < krem)        { shbuf[8] = 4u*tid + 1u; shbuf[9] = krem - s2; }
    if (s2 >= krem && s3 < krem)        { shbuf[8] = 4u*tid + 2u; shbuf[9] = krem - s3; }
    if (s3 >= krem && suf_after < krem) { shbuf[8] = 4u*tid + 3u; shbuf[9] = krem - suf_after; }
    __syncthreads();
    digit = shbuf[8]; newkrem = shbuf[9];
}

// ---------------- pass 1: pred_n + positive counts + radix pass-0 hist ------
// 8 pixels/thread, grid (200, 8)
__global__ void k_predn(const float* __restrict__ preds,
                        const int*   __restrict__ mask) {
    __shared__ unsigned sh[NBIN];
    int tid = threadIdx.x;
    ((uint4*)sh)[tid] = make_uint4(0, 0, 0, 0);
    __syncthreads();

    int s = blockIdx.y;
    int cnt = 0;
    #pragma unroll
    for (int it = 0; it < 2; it++) {
        int i = (blockIdx.x * 512 + it * 256 + tid) * 4;
        const float4 x = *(const float4*)(preds + ((size_t)s * NCH + 6) * PIX + i);
        const int4   m = *(const int4*)(mask + (size_t)s * PIX + i);
        float pn[4];
        pn[0] = sigmoidf(x.x) * (float)m.x;
        pn[1] = sigmoidf(x.y) * (float)m.y;
        pn[2] = sigmoidf(x.z) * (float)m.z;
        pn[3] = sigmoidf(x.w) * (float)m.w;
        *(float4*)(g_predn + (size_t)s * PIX + i) = make_float4(pn[0], pn[1], pn[2], pn[3]);
        #pragma unroll
        for (int j = 0; j < 4; j++) {
            bool isneg = pn[j] < 0.5f;
            cnt += !isneg;
            hist_add(sh, isneg, __float_as_uint(pn[j]) >> 20);
        }
    }
    #pragma unroll
    for (int o = 16; o; o >>= 1) cnt += __shfl_down_sync(0xffffffffu, cnt, o);
    if ((tid & 31) == 0 && cnt) atomicAdd(&g_npos[s], cnt);

    __syncthreads();
    #pragma unroll
    for (int b = tid; b < NBIN; b += 256) {
        unsigned c = sh[b];
        if (c) atomicAdd(&g_histA[s][b], c);
    }
}

// ---------------- radix pass 1: pick d0 from histA, histogram into histB ----
__global__ void k_hist1() {
    int s = blockIdx.y;
    unsigned k;
    if (!ohem_active(s, k)) return;

    __shared__ unsigned sh[NBIN];
    __shared__ unsigned shbuf[10];
    int tid = threadIdx.x;
    ((uint4*)sh)[tid] = make_uint4(0, 0, 0, 0);
    // radix_pick's barriers also order the smem zeroing
    unsigned d0, krem0;
    radix_pick(g_histA[s], k, shbuf, d0, krem0);
    if (blockIdx.x == 0 && tid == 0) { g_d0[s] = d0; g_krem0[s] = krem0; }

    #pragma unroll
    for (int it = 0; it < 2; it++) {
        int i = (blockIdx.x * 512 + it * 256 + tid) * 4;
        float4 v = *(const float4*)(g_predn + (size_t)s * PIX + i);
        float vv[4] = {v.x, v.y, v.z, v.w};
        #pragma unroll
        for (int j = 0; j < 4; j++) {
            unsigned b = __float_as_uint(vv[j]);
            bool hit = (vv[j] < 0.5f) && ((b >> 20) == d0);
            hist_add(sh, hit, (b >> 10) & (NBIN - 1u));
        }
    }
    __syncthreads();
    #pragma unroll
    for (int b = tid; b < NBIN; b += 256) {
        unsigned c = sh[b];
        if (c) atomicAdd(&g_histB[s][b], c);
    }
}

// ---------------- radix pass 2: pick d1 from histB, histogram into histC ----
__global__ void k_hist2() {
    int s = blockIdx.y;
    unsigned k;
    if (!ohem_active(s, k)) return;

    __shared__ unsigned sh[NBIN];
    __shared__ unsigned shbuf[10];
    int tid = threadIdx.x;
    ((uint4*)sh)[tid] = make_uint4(0, 0, 0, 0);
    unsigned d1, krem1;
    radix_pick(g_histB[s], g_krem0[s], shbuf, d1, krem1);
    unsigned pref1 = (g_d0[s] << 10) | d1;
    if (blockIdx.x == 0 && tid == 0) { g_pref1[s] = pref1; g_krem1[s] = krem1; }

    #pragma unroll
    for (int it = 0; it < 2; it++) {
        int i = (blockIdx.x * 512 + it * 256 + tid) * 4;
        float4 v = *(const float4*)(g_predn + (size_t)s * PIX + i);
        float vv[4] = {v.x, v.y, v.z, v.w};
        #pragma unroll
        for (int j = 0; j < 4; j++) {
            unsigned b = __float_as_uint(vv[j]);
            bool hit = (vv[j] < 0.5f) && ((b >> 10) == pref1);
            hist_add(sh, hit, b & (NBIN - 1u));
        }
    }
    __syncthreads();
    #pragma unroll
    for (int b = tid; b < NBIN; b += 256) {
        unsigned c = sh[b];
        if (c) atomicAdd(&g_histC[s][b], c);
    }
}

// ---------------- fused: final pick + dice reductions + compose + reset -----
__global__ void k_reduce(const float* __restrict__ preds,
                         const int*   __restrict__ labels,
                         const int*   __restrict__ mask,
                         float* __restrict__ out) {
    __shared__ unsigned shbuf[10];
    __shared__ float shred[8][21];
    __shared__ bool  is_last;

    int s = blockIdx.y;
    int tid = threadIdx.x;
    unsigned k;
    bool act = ohem_active(s, k);
    float thr = 0.f;
    if (act) {
        unsigned d2, dummy;
        radix_pick(g_histC[s], g_krem1[s], shbuf, d2, dummy);
        thr = __uint_as_float((g_pref1[s] << 10) | d2);   // exact 30-bit key
    }

    int i = (blockIdx.x * blockDim.x + tid) * 4;
    size_t sbase = (size_t)s * NCH * PIX;

    float4 pn4 = *(const float4*)(g_predn + (size_t)s * PIX + i);
    int4   m4  = *(const int4*)(mask + (size_t)s * PIX + i);
    int4   l64 = *(const int4*)(labels + sbase + (size_t)6 * PIX + i);
    float pn[4] = {pn4.x, pn4.y, pn4.z, pn4.w};
    int   mm[4] = {m4.x, m4.y, m4.z, m4.w};
    int   l6[4] = {l64.x, l64.y, l64.z, l64.w};

    float acc[21];
    #pragma unroll
    for (int t = 0; t < 21; t++) acc[t] = 0.f;

    float W[4];
    #pragma unroll
    for (int j = 0; j < 4; j++) {
        float M = act ? (pn[j] >= thr ? 1.f : 0.f) : 1.f;
        W[j] = (pn[j] >= 0.5f) ? 1.f : 0.f;
        float ln = (float)(l6[j] * mm[j]);
        acc[0] += pn[j] * ln * M;
        acc[1] += pn[j] * pn[j] * M;
        acc[2] += ln * M;
    }
    #pragma unroll
    for (int c = 0; c < 6; c++) {
        float4 x4  = *(const float4*)(preds  + sbase + (size_t)c * PIX + i);
        int4   lc4 = *(const int4*)(labels + sbase + (size_t)c * PIX + i);
        float xv[4] = {x4.x, x4.y, x4.z, x4.w};
        int   lv[4] = {lc4.x, lc4.y, lc4.z, lc4.w};
        #pragma unroll
        for (int j = 0; j < 4; j++) {
            float pc = sigmoidf(xv[j]);
            float lf = (float)lv[j];
            float w  = W[j];
            acc[3 + 3 * c + 0] += pc * lf * w;
            acc[3 + 3 * c + 1] += pc * pc * w;
            acc[3 + 3 * c + 2] += lf * w;
        }
    }

    int lane = tid & 31, warp = tid >> 5;
    #pragma unroll
    for (int t = 0; t < 21; t++) {
        float v = acc[t];
        #pragma unroll
        for (int o = 16; o; o >>= 1) v += __shfl_down_sync(0xffffffffu, v, o);
        if (lane == 0) shred[warp][t] = v;
    }
    __syncthreads();
    if (tid < 21) {
        float v = 0.f;
        #pragma unroll
        for (int w = 0; w < 8; w++) v += shred[w][tid];
        atomicAdd(&g_acc[s][tid], v);
    }

    __threadfence();
    if (tid == 0) {
        unsigned total = gridDim.x * gridDim.y;
        is_last = (atomicAdd(&g_counter, 1u) == total - 1);
    }
    __syncthreads();
    if (is_last) {
        // zero radix state for next replay (all reduce blocks already done)
        for (int b = tid; b < S * NBIN; b += 256) {
            ((unsigned*)g_histA)[b] = 0u;
            ((unsigned*)g_histB)[b] = 0u;
            ((unsigned*)g_histC)[b] = 0u;
        }
        if (tid < S) g_npos[tid] = 0;
        if (tid == 0) {
            float Lc_s = 0.f, Ls_s = 0.f, loss_s = 0.f;
            for (int ss = 0; ss < S; ss++) {
                float a[21];
                for (int t = 0; t < 21; t++) {
                    a[t] = __ldcg(&g_acc[ss][t]);
                    g_acc[ss][t] = 0.f;
                }
                float Lc = 1.f - (2.f * a[0]) / (a[1] + a[2] + EPSV);
                float d = 0.f;
                for (int c = 0; c < 6; c++)
                    d += (2.f * a[3 + 3 * c]) / (a[4 + 3 * c] + a[5 + 3 * c] + EPSV);
                float Ls = 1.f - d / 6.f;
                Lc_s += Lc; Ls_s += Ls;
                loss_s += LAMBDA * Lc + (1.f - LAMBDA) * Ls;
            }
            out[0] = Lc_s / (float)S;
            out[1] = Ls_s / (float)S;
            out[2] = loss_s / (float)S;
            g_counter = 0u;
        }
    }
}

// ---------------- launch ----------------
extern "C" void kernel_launch(void* const* d_in, const int* in_sizes, int n_in,
                              void* d_out, int out_size) {
    const float* preds  = (const float*)d_in[0];
    const int*   labels = (const int*)d_in[1];
    const int*   mask   = (const int*)d_in[2];
    float* out = (float*)d_out;

    k_predn<<<dim3(200, S), 256>>>(preds, mask);
    k_hist1<<<dim3(200, S), 256>>>();
    k_hist2<<<dim3(200, S), 256>>>();
    k_reduce<<<dim3(400, S), 256>>>(preds, labels, mask, out);
    (void)in_sizes; (void)n_in; (void)out_size;
}

// round 4
// speedup vs baseline: 1.0314x; 1.0314x over previous
#include <cuda_runtime.h>

// Problem constants
#define S    8
#define NCH  7
#define PIX  409600           // 640*640
#define NCHUNK (PIX / 128)    // 3200 warp-chunks of 128 px
#define LAMBDA 0.7f
#define EPSV 1e-6f
#define NBIN 1024             // 10-bit radix digits; key is 30 bits (value in [0,0.5))

// ---------------- device scratch (zero at module load; reduce's last block
// restores the zero invariant each replay) --------------------------------
__device__ float    g_predn[S * PIX];
__device__ uint4    g_wbits[S * NCHUNK];              // W=(pn>=0.5) bitmask, 4x32b per 128px
__device__ int      g_npos[S];
__device__ __align__(16) unsigned g_histA[S][NBIN];   // pass 0 (key>>20)
__device__ __align__(16) unsigned g_histB[S][NBIN];   // pass 1 ((key>>10)&1023)
__device__ __align__(16) unsigned g_histC[S][NBIN];   // pass 2 (key&1023)
__device__ unsigned g_d0[S], g_krem0[S];
__device__ unsigned g_pref1[S], g_krem1[S];
__device__ float    g_acc[S][21];                     // [0..2]=Lc, [3+3c..]=Ls per channel
__device__ unsigned g_counter;

__device__ __forceinline__ float sigmoidf(float x) {
    return 1.f / (1.f + __expf(-x));
}

__device__ __forceinline__ bool ohem_active(int s, unsigned& k) {
    int np = g_npos[s];
    k = (unsigned)(np * 3);
    return ((unsigned)(PIX - np) > k) && (k > 0);
}

// Warp-dedup'd shared histogram add: one atomic per distinct bin per warp.
__device__ __forceinline__ void hist_add(unsigned* sh, bool participate, unsigned bin) {
    unsigned ballot = __ballot_sync(0xffffffffu, participate);
    if (participate) {
        unsigned grp = __match_any_sync(ballot, bin);
        int leader = __ffs(grp) - 1;
        if ((int)(threadIdx.x & 31) == leader)
            atomicAdd(&sh[bin], (unsigned)__popc(grp));
    }
}

// Radix digit pick over a 1024-bin histogram row, 256 threads, 2 barriers.
__device__ __forceinline__ void radix_pick(const unsigned* __restrict__ hrow,
                                           unsigned krem,
                                           unsigned* shbuf,     // >= 10 words
                                           unsigned& digit, unsigned& newkrem) {
    int tid = threadIdx.x, lane = tid & 31, w = tid >> 5;
    uint4 h = ((const uint4*)hrow)[tid];           // bins 4t .. 4t+3
    unsigned local = h.x + h.y + h.z + h.w;
    unsigned v = local;                            // warp inclusive suffix sum
    #pragma unroll
    for (int o = 1; o < 32; o <<= 1) {
        unsigned u = __shfl_down_sync(0xffffffffu, v, o);
        if (lane + o < 32) v += u;
    }
    if (lane == 0) shbuf[w] = v;
    __syncthreads();
    unsigned after_w = 0;
    #pragma unroll
    for (int j = 0; j < 8; j++) if (j > w) after_w += shbuf[j];
    unsigned suf_me    = v + after_w;
    unsigned suf_after = suf_me - local;
    unsigned s3 = h.w + suf_after;
    unsigned s2 = h.z + s3;
    unsigned s1 = h.y + s2;
    unsigned s0 = h.x + s1;
    if (s0 >= krem && s1 < krem)        { shbuf[8] = 4u*tid + 0u; shbuf[9] = krem - s1; }
    if (s1 >= krem && s2 < krem)        { shbuf[8] = 4u*tid + 1u; shbuf[9] = krem - s2; }
    if (s2 >= krem && s3 < krem)        { shbuf[8] = 4u*tid + 2u; shbuf[9] = krem - s3; }
    if (s3 >= krem && suf_after < krem) { shbuf[8] = 4u*tid + 3u; shbuf[9] = krem - suf_after; }
    __syncthreads();
    digit = shbuf[8]; newkrem = shbuf[9];
}

// ---------------- pass 1: pred_n + W bitmask + npos + radix pass-0 hist -----
__global__ void k_predn(const float* __restrict__ preds,
                        const int*   __restrict__ mask) {
    __shared__ unsigned sh[NBIN];
    int tid = threadIdx.x, lane = tid & 31;
    ((uint4*)sh)[tid] = make_uint4(0, 0, 0, 0);
    __syncthreads();

    int s = blockIdx.y;
    int cnt = 0;
    #pragma unroll
    for (int it = 0; it < 2; it++) {
        int e = blockIdx.x * 512 + it * 256 + tid;   // float4 index
        int i = e * 4;
        const float4 x = *(const float4*)(preds + (size_t)(s * NCH + 6) * PIX + i);
        const int4   m = *(const int4*)(mask + (size_t)s * PIX + i);
        float pn[4];
        pn[0] = sigmoidf(x.x) * (float)m.x;
        pn[1] = sigmoidf(x.y) * (float)m.y;
        pn[2] = sigmoidf(x.z) * (float)m.z;
        pn[3] = sigmoidf(x.w) * (float)m.w;
        *(float4*)(g_predn + (size_t)s * PIX + i) = make_float4(pn[0], pn[1], pn[2], pn[3]);
        unsigned wb[4];
        #pragma unroll
        for (int j = 0; j < 4; j++) {
            bool ispos = pn[j] >= 0.5f;
            cnt += ispos;
            wb[j] = __ballot_sync(0xffffffffu, ispos);
            hist_add(sh, !ispos, __float_as_uint(pn[j]) >> 20);
        }
        if (lane == 0)
            g_wbits[s * NCHUNK + (e >> 5)] = make_uint4(wb[0], wb[1], wb[2], wb[3]);
    }
    #pragma unroll
    for (int o = 16; o; o >>= 1) cnt += __shfl_down_sync(0xffffffffu, cnt, o);
    if (lane == 0 && cnt) atomicAdd(&g_npos[s], cnt);

    __syncthreads();
    #pragma unroll
    for (int b = tid; b < NBIN; b += 256) {
        unsigned c = sh[b];
        if (c) atomicAdd(&g_histA[s][b], c);
    }
}

// ---------------- radix pass 1: pick d0 from histA, histogram into histB ----
__global__ void k_hist1() {
    int s = blockIdx.y;
    unsigned k;
    if (!ohem_active(s, k)) return;

    __shared__ unsigned sh[NBIN];
    __shared__ unsigned shbuf[10];
    int tid = threadIdx.x;
    ((uint4*)sh)[tid] = make_uint4(0, 0, 0, 0);
    unsigned d0, krem0;
    radix_pick(g_histA[s], k, shbuf, d0, krem0);   // barriers also order smem zeroing
    if (blockIdx.x == 0 && tid == 0) { g_d0[s] = d0; g_krem0[s] = krem0; }

    #pragma unroll
    for (int it = 0; it < 2; it++) {
        int i = (blockIdx.x * 512 + it * 256 + tid) * 4;
        float4 v = *(const float4*)(g_predn + (size_t)s * PIX + i);
        float vv[4] = {v.x, v.y, v.z, v.w};
        #pragma unroll
        for (int j = 0; j < 4; j++) {
            unsigned b = __float_as_uint(vv[j]);
            bool hit = (vv[j] < 0.5f) && ((b >> 20) == d0);
            hist_add(sh, hit, (b >> 10) & (NBIN - 1u));
        }
    }
    __syncthreads();
    #pragma unroll
    for (int b = tid; b < NBIN; b += 256) {
        unsigned c = sh[b];
        if (c) atomicAdd(&g_histB[s][b], c);
    }
}

// ---------------- radix pass 2: pick d1 from histB, histogram into histC ----
__global__ void k_hist2() {
    int s = blockIdx.y;
    unsigned k;
    if (!ohem_active(s, k)) return;

    __shared__ unsigned sh[NBIN];
    __shared__ unsigned shbuf[10];
    int tid = threadIdx.x;
    ((uint4*)sh)[tid] = make_uint4(0, 0, 0, 0);
    unsigned d1, krem1;
    radix_pick(g_histB[s], g_krem0[s], shbuf, d1, krem1);
    unsigned pref1 = (g_d0[s] << 10) | d1;
    if (blockIdx.x == 0 && tid == 0) { g_pref1[s] = pref1; g_krem1[s] = krem1; }

    #pragma unroll
    for (int it = 0; it < 2; it++) {
        int i = (blockIdx.x * 512 + it * 256 + tid) * 4;
        float4 v = *(const float4*)(g_predn + (size_t)s * PIX + i);
        float vv[4] = {v.x, v.y, v.z, v.w};
        #pragma unroll
        for (int j = 0; j < 4; j++) {
            unsigned b = __float_as_uint(vv[j]);
            bool hit = (vv[j] < 0.5f) && ((b >> 10) == pref1);
            hist_add(sh, hit, b & (NBIN - 1u));
        }
    }
    __syncthreads();
    #pragma unroll
    for (int b = tid; b < NBIN; b += 256) {
        unsigned c = sh[b];
        if (c) atomicAdd(&g_histC[s][b], c);
    }
}

// ---------------- channel-split reduce: z<6 = Ls channel, z=6 = Lc ---------
__global__ void __launch_bounds__(256) k_reduce(const float* __restrict__ preds,
                         const int*   __restrict__ labels,
                         const int*   __restrict__ mask,
                         float* __restrict__ out) {
    __shared__ unsigned shbuf[10];
    __shared__ float shred[8][3];
    __shared__ bool  is_last;

    int s = blockIdx.y, c = blockIdx.z;
    int tid = threadIdx.x, lane = tid & 31, warp = tid >> 5;
    float a0 = 0.f, a1 = 0.f, a2 = 0.f;
    int slot;

    if (c < 6) {
        // ---- Ls channel c: stream preds[s,c] + labels[s,c] + Wbits --------
        slot = 3 + 3 * c;
        float4 x[2]; int4 l[2]; uint4 wb[2];
        int ebase = blockIdx.x * 512 + tid;
        int base = (s * NCH + c) * PIX;
        #pragma unroll
        for (int it = 0; it < 2; it++) {
            int e = ebase + it * 256;
            wb[it] = g_wbits[s * NCHUNK + (e >> 5)];
            x[it]  = *(const float4*)(preds  + (size_t)base + e * 4);
            l[it]  = *(const int4*)(labels + (size_t)base + e * 4);
        }
        #pragma unroll
        for (int it = 0; it < 2; it++) {
            float xv[4] = {x[it].x, x[it].y, x[it].z, x[it].w};
            int   lv[4] = {l[it].x, l[it].y, l[it].z, l[it].w};
            unsigned wv[4] = {wb[it].x, wb[it].y, wb[it].z, wb[it].w};
            #pragma unroll
            for (int j = 0; j < 4; j++) {
                float w  = (float)((wv[j] >> lane) & 1u);
                float pc = sigmoidf(xv[j]) * w;
                float lf = (float)lv[j] * w;
                a0 += pc * lf;
                a1 += pc * pc;
                a2 += lf;   // lf*lf == lf (0/1)
            }
        }
    } else {
        // ---- Lc: needs OHEM threshold ------------------------------------
        slot = 0;
        unsigned k;
        bool act = ohem_active(s, k);
        float thr = 0.f;
        if (act) {
            unsigned d2, dummy;
            radix_pick(g_histC[s], g_krem1[s], shbuf, d2, dummy);
            thr = __uint_as_float((g_pref1[s] << 10) | d2);   // exact 30-bit key
        }
        float4 p[2]; int4 l[2]; int4 m[2];
        int ebase = blockIdx.x * 512 + tid;
        #pragma unroll
        for (int it = 0; it < 2; it++) {
            int e = ebase + it * 256;
            p[it] = *(const float4*)(g_predn + (size_t)s * PIX + e * 4);
            l[it] = *(const int4*)(labels + (size_t)(s * NCH + 6) * PIX + e * 4);
            m[it] = *(const int4*)(mask + (size_t)s * PIX + e * 4);
        }
        #pragma unroll
        for (int it = 0; it < 2; it++) {
            float pv[4] = {p[it].x, p[it].y, p[it].z, p[it].w};
            int   lv[4] = {l[it].x, l[it].y, l[it].z, l[it].w};
            int   mv[4] = {m[it].x, m[it].y, m[it].z, m[it].w};
            #pragma unroll
            for (int j = 0; j < 4; j++) {
                float M = act ? (pv[j] >= thr ? 1.f : 0.f) : 1.f;
                float ln = (float)(lv[j] * mv[j]) * M;
                float pm = pv[j] * M;
                a0 += pm * ln;
                a1 += pm * pv[j];   // pn^2 * M  (M^2==M)
                a2 += ln;           // ln^2 == ln
            }
        }
    }

    // block reduce 3 accumulators
    #pragma unroll
    for (int o = 16; o; o >>= 1) {
        a0 += __shfl_down_sync(0xffffffffu, a0, o);
        a1 += __shfl_down_sync(0xffffffffu, a1, o);
        a2 += __shfl_down_sync(0xffffffffu, a2, o);
    }
    if (lane == 0) { shred[warp][0] = a0; shred[warp][1] = a1; shred[warp][2] = a2; }
    __syncthreads();
    if (tid < 3) {
        float v = 0.f;
        #pragma unroll
        for (int w = 0; w < 8; w++) v += shred[w][tid];
        atomicAdd(&g_acc[s][slot + tid], v);
    }

    __threadfence();
    if (tid == 0) {
        unsigned total = gridDim.x * gridDim.y * gridDim.z;
        is_last = (atomicAdd(&g_counter, 1u) == total - 1);
    }
    __syncthreads();
    if (is_last) {
        for (int b = tid; b < S * NBIN; b += 256) {
            ((unsigned*)g_histA)[b] = 0u;
            ((unsigned*)g_histB)[b] = 0u;
            ((unsigned*)g_histC)[b] = 0u;
        }
        if (tid < S) g_npos[tid] = 0;
        if (tid == 0) {
            float Lc_s = 0.f, Ls_s = 0.f, loss_s = 0.f;
            for (int ss = 0; ss < S; ss++) {
                float a[21];
                for (int t = 0; t < 21; t++) {
                    a[t] = __ldcg(&g_acc[ss][t]);
                    g_acc[ss][t] = 0.f;
                }
                float Lc = 1.f - (2.f * a[0]) / (a[1] + a[2] + EPSV);
                float d = 0.f;
                for (int cc = 0; cc < 6; cc++)
                    d += (2.f * a[3 + 3 * cc]) / (a[4 + 3 * cc] + a[5 + 3 * cc] + EPSV);
                float Ls = 1.f - d / 6.f;
                Lc_s += Lc; Ls_s += Ls;
                loss_s += LAMBDA * Lc + (1.f - LAMBDA) * Ls;
            }
            out[0] = Lc_s / (float)S;
            out[1] = Ls_s / (float)S;
            out[2] = loss_s / (float)S;
            g_counter = 0u;
        }
    }
}

// ---------------- launch ----------------
extern "C" void kernel_launch(void* const* d_in, const int* in_sizes, int n_in,
                              void* d_out, int out_size) {
    const float* preds  = (const float*)d_in[0];
    const int*   labels = (const int*)d_in[1];
    const int*   mask   = (const int*)d_in[2];
    float* out = (float*)d_out;

    k_predn<<<dim3(200, S), 256>>>(preds, mask);
    k_hist1<<<dim3(200, S), 256>>>();
    k_hist2<<<dim3(200, S), 256>>>();
    k_reduce<<<dim3(200, S, 7), 256>>>(preds, labels, mask, out);
    (void)in_sizes; (void)n_in; (void)out_size;
}

// round 5
// speedup vs baseline: 1.0935x; 1.0603x over previous
#include <cuda_runtime.h>

// Problem constants
#define S    8
#define NCH  7
#define PIX  409600           // 640*640
#define NCHUNK (PIX / 128)    // 3200 warp-chunks of 128 px
#define LAMBDA 0.7f
#define EPSV 1e-6f
#define NBIN 1024             // 10-bit radix digits; key is 30 bits (value in [0,0.5))

// ---------------- device scratch (zero at module load; reduce's last block
// restores the zero invariant each replay) --------------------------------
__device__ float    g_predn[S * PIX];
__device__ uint4    g_wbits[S * NCHUNK];              // W=(pn>=0.5) bitmask, 4x32b per 128px
__device__ int      g_npos[S];
__device__ __align__(16) unsigned g_histA[S][NBIN];   // pass 0 (key>>20)
__device__ __align__(16) unsigned g_histB[S][NBIN];   // pass 1 ((key>>10)&1023)
__device__ __align__(16) unsigned g_histC[S][NBIN];   // pass 2 (key&1023)
__device__ unsigned g_d0[S], g_krem0[S];
__device__ unsigned g_pref1[S], g_krem1[S];
__device__ float    g_acc[S][21];                     // [0..2]=Lc, [3+3c..]=Ls per channel
__device__ unsigned g_counter;

// Division-free sigmoid: 0.5*tanh(0.5x)+0.5 via single-MUFU tanh.approx.
__device__ __forceinline__ float sigmoidf(float x) {
    float t, y = 0.5f * x;
    asm("tanh.approx.f32 %0, %1;" : "=f"(t) : "f"(y));
    return fmaf(0.5f, t, 0.5f);
}

__device__ __forceinline__ bool ohem_active(int s, unsigned& k) {
    int np = g_npos[s];
    k = (unsigned)(np * 3);
    return ((unsigned)(PIX - np) > k) && (k > 0);
}

// Warp-dedup'd shared histogram add: one atomic per distinct bin per warp.
__device__ __forceinline__ void hist_add(unsigned* sh, bool participate, unsigned bin) {
    unsigned ballot = __ballot_sync(0xffffffffu, participate);
    if (participate) {
        unsigned grp = __match_any_sync(ballot, bin);
        int leader = __ffs(grp) - 1;
        if ((int)(threadIdx.x & 31) == leader)
            atomicAdd(&sh[bin], (unsigned)__popc(grp));
    }
}

// Radix digit pick over a 1024-bin histogram row, 256 threads, 2 barriers.
__device__ __forceinline__ void radix_pick(const unsigned* __restrict__ hrow,
                                           unsigned krem,
                                           unsigned* shbuf,     // >= 10 words
                                           unsigned& digit, unsigned& newkrem) {
    int tid = threadIdx.x, lane = tid & 31, w = tid >> 5;
    uint4 h = ((const uint4*)hrow)[tid];           // bins 4t .. 4t+3
    unsigned local = h.x + h.y + h.z + h.w;
    unsigned v = local;                            // warp inclusive suffix sum
    #pragma unroll
    for (int o = 1; o < 32; o <<= 1) {
        unsigned u = __shfl_down_sync(0xffffffffu, v, o);
        if (lane + o < 32) v += u;
    }
    if (lane == 0) shbuf[w] = v;
    __syncthreads();
    unsigned after_w = 0;
    #pragma unroll
    for (int j = 0; j < 8; j++) if (j > w) after_w += shbuf[j];
    unsigned suf_me    = v + after_w;
    unsigned suf_after = suf_me - local;
    unsigned s3 = h.w + suf_after;
    unsigned s2 = h.z + s3;
    unsigned s1 = h.y + s2;
    unsigned s0 = h.x + s1;
    if (s0 >= krem && s1 < krem)        { shbuf[8] = 4u*tid + 0u; shbuf[9] = krem - s1; }
    if (s1 >= krem && s2 < krem)        { shbuf[8] = 4u*tid + 1u; shbuf[9] = krem - s2; }
    if (s2 >= krem && s3 < krem)        { shbuf[8] = 4u*tid + 2u; shbuf[9] = krem - s3; }
    if (s3 >= krem && suf_after < krem) { shbuf[8] = 4u*tid + 3u; shbuf[9] = krem - suf_after; }
    __syncthreads();
    digit = shbuf[8]; newkrem = shbuf[9];
}

// ---------------- pass 1: pred_n + W bitmask + npos + radix pass-0 hist -----
__global__ void k_predn(const float* __restrict__ preds,
                        const int*   __restrict__ mask) {
    __shared__ unsigned sh[NBIN];
    int tid = threadIdx.x, lane = tid & 31;
    ((uint4*)sh)[tid] = make_uint4(0, 0, 0, 0);
    __syncthreads();

    int s = blockIdx.y;
    int cnt = 0;
    #pragma unroll
    for (int it = 0; it < 2; it++) {
        int e = blockIdx.x * 512 + it * 256 + tid;   // float4 index
        int i = e * 4;
        const float4 x = *(const float4*)(preds + (size_t)(s * NCH + 6) * PIX + i);
        const int4   m = *(const int4*)(mask + (size_t)s * PIX + i);
        float pn[4];
        pn[0] = sigmoidf(x.x) * (float)m.x;
        pn[1] = sigmoidf(x.y) * (float)m.y;
        pn[2] = sigmoidf(x.z) * (float)m.z;
        pn[3] = sigmoidf(x.w) * (float)m.w;
        *(float4*)(g_predn + (size_t)s * PIX + i) = make_float4(pn[0], pn[1], pn[2], pn[3]);
        unsigned wb[4];
        #pragma unroll
        for (int j = 0; j < 4; j++) {
            bool ispos = pn[j] >= 0.5f;
            cnt += ispos;
            wb[j] = __ballot_sync(0xffffffffu, ispos);
            hist_add(sh, !ispos, __float_as_uint(pn[j]) >> 20);
        }
        if (lane == 0)
            g_wbits[s * NCHUNK + (e >> 5)] = make_uint4(wb[0], wb[1], wb[2], wb[3]);
    }
    #pragma unroll
    for (int o = 16; o; o >>= 1) cnt += __shfl_down_sync(0xffffffffu, cnt, o);
    if (lane == 0 && cnt) atomicAdd(&g_npos[s], cnt);

    __syncthreads();
    #pragma unroll
    for (int b = tid; b < NBIN; b += 256) {
        unsigned c = sh[b];
        if (c) atomicAdd(&g_histA[s][b], c);
    }
}

// ---------------- radix pass 1: pick d0 from histA, histogram into histB ----
__global__ void k_hist1() {
    int s = blockIdx.y;
    unsigned k;
    if (!ohem_active(s, k)) return;

    __shared__ unsigned sh[NBIN];
    __shared__ unsigned shbuf[10];
    int tid = threadIdx.x;
    ((uint4*)sh)[tid] = make_uint4(0, 0, 0, 0);
    unsigned d0, krem0;
    radix_pick(g_histA[s], k, shbuf, d0, krem0);   // barriers also order smem zeroing
    if (blockIdx.x == 0 && tid == 0) { g_d0[s] = d0; g_krem0[s] = krem0; }

    #pragma unroll
    for (int it = 0; it < 2; it++) {
        int i = (blockIdx.x * 512 + it * 256 + tid) * 4;
        float4 v = *(const float4*)(g_predn + (size_t)s * PIX + i);
        float vv[4] = {v.x, v.y, v.z, v.w};
        #pragma unroll
        for (int j = 0; j < 4; j++) {
            unsigned b = __float_as_uint(vv[j]);
            bool hit = (vv[j] < 0.5f) && ((b >> 20) == d0);
            hist_add(sh, hit, (b >> 10) & (NBIN - 1u));
        }
    }
    __syncthreads();
    #pragma unroll
    for (int b = tid; b < NBIN; b += 256) {
        unsigned c = sh[b];
        if (c) atomicAdd(&g_histB[s][b], c);
    }
}

// ---------------- radix pass 2: pick d1 from histB, histogram into histC ----
__global__ void k_hist2() {
    int s = blockIdx.y;
    unsigned k;
    if (!ohem_active(s, k)) return;

    __shared__ unsigned sh[NBIN];
    __shared__ unsigned shbuf[10];
    int tid = threadIdx.x;
    ((uint4*)sh)[tid] = make_uint4(0, 0, 0, 0);
    unsigned d1, krem1;
    radix_pick(g_histB[s], g_krem0[s], shbuf, d1, krem1);
    unsigned pref1 = (g_d0[s] << 10) | d1;
    if (blockIdx.x == 0 && tid == 0) { g_pref1[s] = pref1; g_krem1[s] = krem1; }

    #pragma unroll
    for (int it = 0; it < 2; it++) {
        int i = (blockIdx.x * 512 + it * 256 + tid) * 4;
        float4 v = *(const float4*)(g_predn + (size_t)s * PIX + i);
        float vv[4] = {v.x, v.y, v.z, v.w};
        #pragma unroll
        for (int j = 0; j < 4; j++) {
            unsigned b = __float_as_uint(vv[j]);
            bool hit = (vv[j] < 0.5f) && ((b >> 10) == pref1);
            hist_add(sh, hit, b & (NBIN - 1u));
        }
    }
    __syncthreads();
    #pragma unroll
    for (int b = tid; b < NBIN; b += 256) {
        unsigned c = sh[b];
        if (c) atomicAdd(&g_histC[s][b], c);
    }
}

// ---------------- channel-split reduce: z<6 = Ls channel, z=6 = Lc ---------
// 16 px/thread, grid (100, S, 7)
__global__ void __launch_bounds__(256) k_reduce(const float* __restrict__ preds,
                         const int*   __restrict__ labels,
                         const int*   __restrict__ mask,
                         float* __restrict__ out) {
    __shared__ unsigned shbuf[10];
    __shared__ float shred[8][3];
    __shared__ bool  is_last;

    int s = blockIdx.y, c = blockIdx.z;
    int tid = threadIdx.x, lane = tid & 31, warp = tid >> 5;
    float a0 = 0.f, a1 = 0.f, a2 = 0.f;
    int slot;
    int ebase = blockIdx.x * 1024 + tid;   // float4 index

    if (c < 6) {
        // ---- Ls channel c: stream preds[s,c] + labels[s,c] + Wbits --------
        slot = 3 + 3 * c;
        float4 x[4]; int4 l[4]; uint4 wb[4];
        int base = (s * NCH + c) * PIX;
        #pragma unroll
        for (int it = 0; it < 4; it++) {
            int e = ebase + it * 256;
            wb[it] = g_wbits[s * NCHUNK + (e >> 5)];
            x[it]  = *(const float4*)(preds  + (size_t)base + e * 4);
            l[it]  = *(const int4*)(labels + (size_t)base + e * 4);
        }
        #pragma unroll
        for (int it = 0; it < 4; it++) {
            float xv[4] = {x[it].x, x[it].y, x[it].z, x[it].w};
            int   lv[4] = {l[it].x, l[it].y, l[it].z, l[it].w};
            unsigned wv[4] = {wb[it].x, wb[it].y, wb[it].z, wb[it].w};
            #pragma unroll
            for (int j = 0; j < 4; j++) {
                float w  = (float)((wv[j] >> lane) & 1u);
                float pc = sigmoidf(xv[j]) * w;
                float lf = (float)lv[j] * w;
                a0 += pc * lf;
                a1 += pc * pc;
                a2 += lf;   // lf*lf == lf (0/1)
            }
        }
    } else {
        // ---- Lc: needs OHEM threshold ------------------------------------
        slot = 0;
        unsigned k;
        bool act = ohem_active(s, k);
        float thr = 0.f;
        if (act) {
            unsigned d2, dummy;
            radix_pick(g_histC[s], g_krem1[s], shbuf, d2, dummy);
            thr = __uint_as_float((g_pref1[s] << 10) | d2);   // exact 30-bit key
        }
        float4 p[4]; int4 l[4]; int4 m[4];
        #pragma unroll
        for (int it = 0; it < 4; it++) {
            int e = ebase + it * 256;
            p[it] = *(const float4*)(g_predn + (size_t)s * PIX + e * 4);
            l[it] = *(const int4*)(labels + (size_t)(s * NCH + 6) * PIX + e * 4);
            m[it] = *(const int4*)(mask + (size_t)s * PIX + e * 4);
        }
        #pragma unroll
        for (int it = 0; it < 4; it++) {
            float pv[4] = {p[it].x, p[it].y, p[it].z, p[it].w};
            int   lv[4] = {l[it].x, l[it].y, l[it].z, l[it].w};
            int   mv[4] = {m[it].x, m[it].y, m[it].z, m[it].w};
            #pragma unroll
            for (int j = 0; j < 4; j++) {
                float M = act ? (pv[j] >= thr ? 1.f : 0.f) : 1.f;
                float ln = (float)(lv[j] * mv[j]) * M;
                float pm = pv[j] * M;
                a0 += pm * ln;
                a1 += pm * pv[j];   // pn^2 * M  (M^2==M)
                a2 += ln;           // ln^2 == ln
            }
        }
    }

    // block reduce 3 accumulators
    #pragma unroll
    for (int o = 16; o; o >>= 1) {
        a0 += __shfl_down_sync(0xffffffffu, a0, o);
        a1 += __shfl_down_sync(0xffffffffu, a1, o);
        a2 += __shfl_down_sync(0xffffffffu, a2, o);
    }
    if (lane == 0) { shred[warp][0] = a0; shred[warp][1] = a1; shred[warp][2] = a2; }
    __syncthreads();
    if (tid < 3) {
        float v = 0.f;
        #pragma unroll
        for (int w = 0; w < 8; w++) v += shred[w][tid];
        atomicAdd(&g_acc[s][slot + tid], v);
    }

    __threadfence();
    if (tid == 0) {
        unsigned total = gridDim.x * gridDim.y * gridDim.z;
        is_last = (atomicAdd(&g_counter, 1u) == total - 1);
    }
    __syncthreads();
    if (is_last) {
        for (int b = tid; b < S * NBIN; b += 256) {
            ((unsigned*)g_histA)[b] = 0u;
            ((unsigned*)g_histB)[b] = 0u;
            ((unsigned*)g_histC)[b] = 0u;
        }
        if (tid < S) g_npos[tid] = 0;
        if (tid == 0) {
            float Lc_s = 0.f, Ls_s = 0.f, loss_s = 0.f;
            for (int ss = 0; ss < S; ss++) {
                float a[21];
                for (int t = 0; t < 21; t++) {
                    a[t] = __ldcg(&g_acc[ss][t]);
                    g_acc[ss][t] = 0.f;
                }
                float Lc = 1.f - (2.f * a[0]) / (a[1] + a[2] + EPSV);
                float d = 0.f;
                for (int cc = 0; cc < 6; cc++)
                    d += (2.f * a[3 + 3 * cc]) / (a[4 + 3 * cc] + a[5 + 3 * cc] + EPSV);
                float Ls = 1.f - d / 6.f;
                Lc_s += Lc; Ls_s += Ls;
                loss_s += LAMBDA * Lc + (1.f - LAMBDA) * Ls;
            }
            out[0] = Lc_s / (float)S;
            out[1] = Ls_s / (float)S;
            out[2] = loss_s / (float)S;
            g_counter = 0u;
        }
    }
}

// ---------------- launch ----------------
extern "C" void kernel_launch(void* const* d_in, const int* in_sizes, int n_in,
                              void* d_out, int out_size) {
    const float* preds  = (const float*)d_in[0];
    const int*   labels = (const int*)d_in[1];
    const int*   mask   = (const int*)d_in[2];
    float* out = (float*)d_out;

    k_predn<<<dim3(200, S), 256>>>(preds, mask);
    k_hist1<<<dim3(200, S), 256>>>();
    k_hist2<<<dim3(200, S), 256>>>();
    k_reduce<<<dim3(100, S, 7), 256>>>(preds, labels, mask, out);
    (void)in_sizes; (void)n_in; (void)out_size;
}

// round 6
// speedup vs baseline: 1.1183x; 1.0227x over previous
#include <cuda_runtime.h>

// Problem constants
#define S    8
#define NCH  7
#define PIX  409600           // 640*640
#define NF4  (PIX / 4)        // 102400 float4 per (s,c) stream
#define NCHUNK (PIX / 128)    // 3200 warp-chunks of 128 px
#define LAMBDA 0.7f
#define EPSV 1e-6f
#define NBIN 1024             // 10-bit radix digits; key is 30 bits (value in [0,0.5))
#define GRIDX 21              // reduce grid.x: 21*8*7=1176 blocks ~= 2 waves @ 4 blk/SM

// ---------------- device scratch (zero at module load; reduce's last block
// restores the zero invariant each replay) --------------------------------
__device__ float    g_predn[S * PIX];
__device__ uint4    g_wbits[S * NCHUNK];              // W=(pn>=0.5) bitmask, 4x32b per 128px
__device__ int      g_npos[S];
__device__ __align__(16) unsigned g_histA[S][NBIN];   // pass 0 (key>>20)
__device__ __align__(16) unsigned g_histB[S][NBIN];   // pass 1 ((key>>10)&1023)
__device__ __align__(16) unsigned g_histC[S][NBIN];   // pass 2 (key&1023)
__device__ unsigned g_d0[S], g_krem0[S];
__device__ unsigned g_pref1[S], g_krem1[S];
__device__ float    g_acc[S][21];                     // [0..2]=Lc, [3+3c..]=Ls per channel
__device__ unsigned g_counter;

// Division-free sigmoid: 0.5*tanh(0.5x)+0.5 via single-MUFU tanh.approx.
__device__ __forceinline__ float sigmoidf(float x) {
    float t, y = 0.5f * x;
    asm("tanh.approx.f32 %0, %1;" : "=f"(t) : "f"(y));
    return fmaf(0.5f, t, 0.5f);
}

__device__ __forceinline__ bool ohem_active(int s, unsigned& k) {
    int np = g_npos[s];
    k = (unsigned)(np * 3);
    return ((unsigned)(PIX - np) > k) && (k > 0);
}

// Warp-dedup'd shared histogram add: one atomic per distinct bin per warp.
__device__ __forceinline__ void hist_add(unsigned* sh, bool participate, unsigned bin) {
    unsigned ballot = __ballot_sync(0xffffffffu, participate);
    if (participate) {
        unsigned grp = __match_any_sync(ballot, bin);
        int leader = __ffs(grp) - 1;
        if ((int)(threadIdx.x & 31) == leader)
            atomicAdd(&sh[bin], (unsigned)__popc(grp));
    }
}

// Radix digit pick over a 1024-bin histogram row, 256 threads, 2 barriers.
__device__ __forceinline__ void radix_pick(const unsigned* __restrict__ hrow,
                                           unsigned krem,
                                           unsigned* shbuf,     // >= 10 words
                                           unsigned& digit, unsigned& newkrem) {
    int tid = threadIdx.x, lane = tid & 31, w = tid >> 5;
    uint4 h = ((const uint4*)hrow)[tid];           // bins 4t .. 4t+3
    unsigned local = h.x + h.y + h.z + h.w;
    unsigned v = local;                            // warp inclusive suffix sum
    #pragma unroll
    for (int o = 1; o < 32; o <<= 1) {
        unsigned u = __shfl_down_sync(0xffffffffu, v, o);
        if (lane + o < 32) v += u;
    }
    if (lane == 0) shbuf[w] = v;
    __syncthreads();
    unsigned after_w = 0;
    #pragma unroll
    for (int j = 0; j < 8; j++) if (j > w) after_w += shbuf[j];
    unsigned suf_me    = v + after_w;
    unsigned suf_after = suf_me - local;
    unsigned s3 = h.w + suf_after;
    unsigned s2 = h.z + s3;
    unsigned s1 = h.y + s2;
    unsigned s0 = h.x + s1;
    if (s0 >= krem && s1 < krem)        { shbuf[8] = 4u*tid + 0u; shbuf[9] = krem - s1; }
    if (s1 >= krem && s2 < krem)        { shbuf[8] = 4u*tid + 1u; shbuf[9] = krem - s2; }
    if (s2 >= krem && s3 < krem)        { shbuf[8] = 4u*tid + 2u; shbuf[9] = krem - s3; }
    if (s3 >= krem && suf_after < krem) { shbuf[8] = 4u*tid + 3u; shbuf[9] = krem - suf_after; }
    __syncthreads();
    digit = shbuf[8]; newkrem = shbuf[9];
}

// ---------------- pass 1: pred_n + W bitmask + npos + radix pass-0 hist -----
__global__ void k_predn(const float* __restrict__ preds,
                        const int*   __restrict__ mask) {
    __shared__ unsigned sh[NBIN];
    int tid = threadIdx.x, lane = tid & 31;
    ((uint4*)sh)[tid] = make_uint4(0, 0, 0, 0);
    __syncthreads();

    int s = blockIdx.y;
    int cnt = 0;
    #pragma unroll
    for (int it = 0; it < 2; it++) {
        int e = blockIdx.x * 512 + it * 256 + tid;   // float4 index
        int i = e * 4;
        const float4 x = *(const float4*)(preds + (size_t)(s * NCH + 6) * PIX + i);
        const int4   m = *(const int4*)(mask + (size_t)s * PIX + i);
        float pn[4];
        pn[0] = sigmoidf(x.x) * (float)m.x;
        pn[1] = sigmoidf(x.y) * (float)m.y;
        pn[2] = sigmoidf(x.z) * (float)m.z;
        pn[3] = sigmoidf(x.w) * (float)m.w;
        *(float4*)(g_predn + (size_t)s * PIX + i) = make_float4(pn[0], pn[1], pn[2], pn[3]);
        unsigned wb[4];
        #pragma unroll
        for (int j = 0; j < 4; j++) {
            bool ispos = pn[j] >= 0.5f;
            cnt += ispos;
            wb[j] = __ballot_sync(0xffffffffu, ispos);
            hist_add(sh, !ispos, __float_as_uint(pn[j]) >> 20);
        }
        if (lane == 0)
            g_wbits[s * NCHUNK + (e >> 5)] = make_uint4(wb[0], wb[1], wb[2], wb[3]);
    }
    #pragma unroll
    for (int o = 16; o; o >>= 1) cnt += __shfl_down_sync(0xffffffffu, cnt, o);
    if (lane == 0 && cnt) atomicAdd(&g_npos[s], cnt);

    __syncthreads();
    #pragma unroll
    for (int b = tid; b < NBIN; b += 256) {
        unsigned c = sh[b];
        if (c) atomicAdd(&g_histA[s][b], c);
    }
}

// ---------------- radix pass 1: pick d0 from histA, histogram into histB ----
__global__ void k_hist1() {
    int s = blockIdx.y;
    unsigned k;
    if (!ohem_active(s, k)) return;

    __shared__ unsigned sh[NBIN];
    __shared__ unsigned shbuf[10];
    int tid = threadIdx.x;
    ((uint4*)sh)[tid] = make_uint4(0, 0, 0, 0);
    unsigned d0, krem0;
    radix_pick(g_histA[s], k, shbuf, d0, krem0);   // barriers also order smem zeroing
    if (blockIdx.x == 0 && tid == 0) { g_d0[s] = d0; g_krem0[s] = krem0; }

    #pragma unroll
    for (int it = 0; it < 2; it++) {
        int i = (blockIdx.x * 512 + it * 256 + tid) * 4;
        float4 v = *(const float4*)(g_predn + (size_t)s * PIX + i);
        float vv[4] = {v.x, v.y, v.z, v.w};
        #pragma unroll
        for (int j = 0; j < 4; j++) {
            unsigned b = __float_as_uint(vv[j]);
            bool hit = (vv[j] < 0.5f) && ((b >> 20) == d0);
            hist_add(sh, hit, (b >> 10) & (NBIN - 1u));
        }
    }
    __syncthreads();
    #pragma unroll
    for (int b = tid; b < NBIN; b += 256) {
        unsigned c = sh[b];
        if (c) atomicAdd(&g_histB[s][b], c);
    }
}

// ---------------- radix pass 2: pick d1 from histB, histogram into histC ----
__global__ void k_hist2() {
    int s = blockIdx.y;
    unsigned k;
    if (!ohem_active(s, k)) return;

    __shared__ unsigned sh[NBIN];
    __shared__ unsigned shbuf[10];
    int tid = threadIdx.x;
    ((uint4*)sh)[tid] = make_uint4(0, 0, 0, 0);
    unsigned d1, krem1;
    radix_pick(g_histB[s], g_krem0[s], shbuf, d1, krem1);
    unsigned pref1 = (g_d0[s] << 10) | d1;
    if (blockIdx.x == 0 && tid == 0) { g_pref1[s] = pref1; g_krem1[s] = krem1; }

    #pragma unroll
    for (int it = 0; it < 2; it++) {
        int i = (blockIdx.x * 512 + it * 256 + tid) * 4;
        float4 v = *(const float4*)(g_predn + (size_t)s * PIX + i);
        float vv[4] = {v.x, v.y, v.z, v.w};
        #pragma unroll
        for (int j = 0; j < 4; j++) {
            unsigned b = __float_as_uint(vv[j]);
            bool hit = (vv[j] < 0.5f) && ((b >> 10) == pref1);
            hist_add(sh, hit, b & (NBIN - 1u));
        }
    }
    __syncthreads();
    #pragma unroll
    for (int b = tid; b < NBIN; b += 256) {
        unsigned c = sh[b];
        if (c) atomicAdd(&g_histC[s][b], c);
    }
}

// ---------------- channel-split reduce: z<6 = Ls channel, z=6 = Lc ---------
// Grid-stride loop, shallow per-thread MLP (avoid multi-CTA L1tex-queue spread)
__global__ void __launch_bounds__(256) k_reduce(const float* __restrict__ preds,
                         const int*   __restrict__ labels,
                         const int*   __restrict__ mask,
                         float* __restrict__ out) {
    __shared__ unsigned shbuf[10];
    __shared__ float shred[8][3];
    __shared__ bool  is_last;

    int s = blockIdx.y, c = blockIdx.z;
    int tid = threadIdx.x, lane = tid & 31, warp = tid >> 5;
    float a0 = 0.f, a1 = 0.f, a2 = 0.f;
    int slot;
    const int e0 = blockIdx.x * 256 + tid;
    const int estride = GRIDX * 256;

    if (c < 6) {
        // ---- Ls channel c: stream preds[s,c] + labels[s,c] + Wbits --------
        slot = 3 + 3 * c;
        const float* pbase = preds + (size_t)(s * NCH + c) * PIX;
        const int*   lbase = labels + (size_t)(s * NCH + c) * PIX;
        const uint4* wbase = g_wbits + s * NCHUNK;
        #pragma unroll 2
        for (int e = e0; e < NF4; e += estride) {
            uint4  wb = wbase[e >> 5];               // warp-broadcast
            float4 x  = __ldcs((const float4*)(pbase + e * 4));
            int4   l  = __ldcs((const int4*)(lbase + e * 4));
            float xv[4] = {x.x, x.y, x.z, x.w};
            int   lv[4] = {l.x, l.y, l.z, l.w};
            unsigned wv[4] = {wb.x, wb.y, wb.z, wb.w};
            #pragma unroll
            for (int j = 0; j < 4; j++) {
                float w  = (float)((wv[j] >> lane) & 1u);
                float pc = sigmoidf(xv[j]) * w;
                float lf = (float)lv[j] * w;
                a0 += pc * lf;
                a1 += pc * pc;
                a2 += lf;   // lf*lf == lf (0/1)
            }
        }
    } else {
        // ---- Lc: needs OHEM threshold ------------------------------------
        slot = 0;
        unsigned k;
        bool act = ohem_active(s, k);
        float thr = 0.f;
        if (act) {
            unsigned d2, dummy;
            radix_pick(g_histC[s], g_krem1[s], shbuf, d2, dummy);
            thr = __uint_as_float((g_pref1[s] << 10) | d2);   // exact 30-bit key
        }
        const float* pnb = g_predn + (size_t)s * PIX;
        const int*   lbase = labels + (size_t)(s * NCH + 6) * PIX;
        const int*   mbase = mask + (size_t)s * PIX;
        #pragma unroll 2
        for (int e = e0; e < NF4; e += estride) {
            float4 p = *(const float4*)(pnb + e * 4);
            int4   l = __ldcs((const int4*)(lbase + e * 4));
            int4   m = __ldcs((const int4*)(mbase + e * 4));
            float pv[4] = {p.x, p.y, p.z, p.w};
            int   lv[4] = {l.x, l.y, l.z, l.w};
            int   mv[4] = {m.x, m.y, m.z, m.w};
            #pragma unroll
            for (int j = 0; j < 4; j++) {
                float M = act ? (pv[j] >= thr ? 1.f : 0.f) : 1.f;
                float ln = (float)(lv[j] * mv[j]) * M;
                float pm = pv[j] * M;
                a0 += pm * ln;
                a1 += pm * pv[j];   // pn^2 * M  (M^2==M)
                a2 += ln;           // ln^2 == ln
            }
        }
    }

    // block reduce 3 accumulators
    #pragma unroll
    for (int o = 16; o; o >>= 1) {
        a0 += __shfl_down_sync(0xffffffffu, a0, o);
        a1 += __shfl_down_sync(0xffffffffu, a1, o);
        a2 += __shfl_down_sync(0xffffffffu, a2, o);
    }
    if (lane == 0) { shred[warp][0] = a0; shred[warp][1] = a1; shred[warp][2] = a2; }
    __syncthreads();
    if (tid < 3) {
        float v = 0.f;
        #pragma unroll
        for (int w = 0; w < 8; w++) v += shred[w][tid];
        atomicAdd(&g_acc[s][slot + tid], v);
    }

    __threadfence();
    if (tid == 0) {
        unsigned total = gridDim.x * gridDim.y * gridDim.z;
        is_last = (atomicAdd(&g_counter, 1u) == total - 1);
    }
    __syncthreads();
    if (is_last) {
        for (int b = tid; b < S * NBIN; b += 256) {
            ((unsigned*)g_histA)[b] = 0u;
            ((unsigned*)g_histB)[b] = 0u;
            ((unsigned*)g_histC)[b] = 0u;
        }
        if (tid < S) g_npos[tid] = 0;
        if (tid == 0) {
            float Lc_s = 0.f, Ls_s = 0.f, loss_s = 0.f;
            for (int ss = 0; ss < S; ss++) {
                float a[21];
                for (int t = 0; t < 21; t++) {
                    a[t] = __ldcg(&g_acc[ss][t]);
                    g_acc[ss][t] = 0.f;
                }
                float Lc = 1.f - (2.f * a[0]) / (a[1] + a[2] + EPSV);
                float d = 0.f;
                for (int cc = 0; cc < 6; cc++)
                    d += (2.f * a[3 + 3 * cc]) / (a[4 + 3 * cc] + a[5 + 3 * cc] + EPSV);
                float Ls = 1.f - d / 6.f;
                Lc_s += Lc; Ls_s += Ls;
                loss_s += LAMBDA * Lc + (1.f - LAMBDA) * Ls;
            }
            out[0] = Lc_s / (float)S;
            out[1] = Ls_s / (float)S;
            out[2] = loss_s / (float)S;
            g_counter = 0u;
        }
    }
}

// ---------------- launch ----------------
extern "C" void kernel_launch(void* const* d_in, const int* in_sizes, int n_in,
                              void* d_out, int out_size) {
    const float* preds  = (const float*)d_in[0];
    const int*   labels = (const int*)d_in[1];
    const int*   mask   = (const int*)d_in[2];
    float* out = (float*)d_out;

    k_predn<<<dim3(200, S), 256>>>(preds, mask);
    k_hist1<<<dim3(200, S), 256>>>();
    k_hist2<<<dim3(200, S), 256>>>();
    k_reduce<<<dim3(GRIDX, S, 7), 256>>>(preds, labels, mask, out);
    (void)in_sizes; (void)n_in; (void)out_size;
}

// round 7
// speedup vs baseline: 1.6749x; 1.4977x over previous
#include <cuda_runtime.h>
#include <cstdint>

// Problem constants
#define S    8
#define NCH  7
#define PIX  409600           // 640*640
#define NCHUNK (PIX / 128)    // 3200 warp-chunks of 128 px
#define LAMBDA 0.7f
#define EPSV 1e-6f
#define NBIN 1024             // 10-bit radix digits; key is 30 bits (value in [0,0.5))

// TMA pipeline config
#define TILE_PX  2048
#define NTILES   (PIX / TILE_PX)     // 200
#define NSTAGE   4
#define LS_STAGE_BYTES (TILE_PX * 8)   // pred f32 + label i32
#define LS_GRIDX 9                     // 9*8*6 = 432 blocks (~3/SM, one wave)
#define LC_STAGE_BYTES (TILE_PX * 12)  // predn + label + mask
#define LC_GRIDX 37                    // 37*8 = 296 blocks (2/SM, one wave)
#define LS_SMEM  (128 + NSTAGE * LS_STAGE_BYTES)   // 65664
#define LC_SMEM  (128 + NSTAGE * LC_STAGE_BYTES)   // 98432

// ---------------- device scratch (zero at module load; lc-final restores) ---
__device__ float    g_predn[S * PIX];
__device__ uint4    g_wbits[S * NCHUNK];
__device__ int      g_npos[S];
__device__ int      g_nzneg[S];                       // negatives with value > 0
__device__ __align__(16) unsigned g_histA[S][NBIN];
__device__ __align__(16) unsigned g_histB[S][NBIN];
__device__ __align__(16) unsigned g_histC[S][NBIN];
__device__ unsigned g_d0[S], g_krem0[S];
__device__ unsigned g_pref1[S], g_krem1[S];
__device__ float    g_acc[S][21];
__device__ unsigned g_counter;

// Division-free sigmoid: 0.5*tanh(0.5x)+0.5 (single MUFU).
__device__ __forceinline__ float sigmoidf(float x) {
    float t, y = 0.5f * x;
    asm("tanh.approx.f32 %0, %1;" : "=f"(t) : "f"(y));
    return fmaf(0.5f, t, 0.5f);
}

// needs_radix: OHEM active AND the k-th largest negative is strictly > 0.
// If active but k > nzneg, the k-th largest negative is exactly 0.0 -> thr=0
// -> M = (pred_n >= 0) = all ones == inactive path. Exact equivalence.
__device__ __forceinline__ bool needs_radix(int s, unsigned& k) {
    int np = g_npos[s];
    k = (unsigned)(np * 3);
    return ((unsigned)(PIX - np) > k) && (k > 0) && (k <= (unsigned)g_nzneg[s]);
}

// ---------------- mbarrier / bulk-async helpers ----------------
__device__ __forceinline__ uint32_t smem_u32(const void* p) {
    return (uint32_t)__cvta_generic_to_shared(p);
}
__device__ __forceinline__ void mbar_init(uint32_t m, uint32_t cnt) {
    asm volatile("mbarrier.init.shared.b64 [%0], %1;" :: "r"(m), "r"(cnt) : "memory");
}
__device__ __forceinline__ void mbar_expect_tx(uint32_t m, uint32_t bytes) {
    asm volatile("mbarrier.arrive.expect_tx.shared.b64 _, [%0], %1;" :: "r"(m), "r"(bytes) : "memory");
}
__device__ __forceinline__ void mbar_wait(uint32_t m, uint32_t parity) {
    asm volatile(
        "{\n\t.reg .pred P;\n\t"
        "WL%=:\n\t"
        "mbarrier.try_wait.parity.acquire.cta.shared::cta.b64 P, [%0], %1, 0x989680;\n\t"
        "@!P bra WL%=;\n\t}"
        :: "r"(m), "r"(parity) : "memory");
}
__device__ __forceinline__ void bulk_g2s(uint32_t dst, const void* src, uint32_t bytes, uint32_t mbar) {
    asm volatile("cp.async.bulk.shared::cluster.global.mbarrier::complete_tx::bytes [%0], [%1], %2, [%3];"
                 :: "r"(dst), "l"(src), "r"(bytes), "r"(mbar) : "memory");
}

// Warp-dedup'd shared histogram add.
__device__ __forceinline__ void hist_add(unsigned* sh, bool participate, unsigned bin) {
    unsigned ballot = __ballot_sync(0xffffffffu, participate);
    if (participate) {
        unsigned grp = __match_any_sync(ballot, bin);
        int leader = __ffs(grp) - 1;
        if ((int)(threadIdx.x & 31) == leader)
            atomicAdd(&sh[bin], (unsigned)__popc(grp));
    }
}

// Radix digit pick over 1024-bin histogram, 256 threads, 2 barriers.
__device__ __forceinline__ void radix_pick(const unsigned* __restrict__ hrow,
                                           unsigned krem, unsigned* shbuf,
                                           unsigned& digit, unsigned& newkrem) {
    int tid = threadIdx.x, lane = tid & 31, w = tid >> 5;
    uint4 h = ((const uint4*)hrow)[tid];
    unsigned local = h.x + h.y + h.z + h.w;
    unsigned v = local;
    #pragma unroll
    for (int o = 1; o < 32; o <<= 1) {
        unsigned u = __shfl_down_sync(0xffffffffu, v, o);
        if (lane + o < 32) v += u;
    }
    if (lane == 0) shbuf[w] = v;
    __syncthreads();
    unsigned after_w = 0;
    #pragma unroll
    for (int j = 0; j < 8; j++) if (j > w) after_w += shbuf[j];
    unsigned suf_me    = v + after_w;
    unsigned suf_after = suf_me - local;
    unsigned s3 = h.w + suf_after;
    unsigned s2 = h.z + s3;
    unsigned s1 = h.y + s2;
    unsigned s0 = h.x + s1;
    if (s0 >= krem && s1 < krem)        { shbuf[8] = 4u*tid + 0u; shbuf[9] = krem - s1; }
    if (s1 >= krem && s2 < krem)        { shbuf[8] = 4u*tid + 1u; shbuf[9] = krem - s2; }
    if (s2 >= krem && s3 < krem)        { shbuf[8] = 4u*tid + 2u; shbuf[9] = krem - s3; }
    if (s3 >= krem && suf_after < krem) { shbuf[8] = 4u*tid + 3u; shbuf[9] = krem - suf_after; }
    __syncthreads();
    digit = shbuf[8]; newkrem = shbuf[9];
}

// ---------------- predn: pred_n + W bits + npos/nzneg + pass-0 hist --------
__global__ void k_predn(const float* __restrict__ preds,
                        const int*   __restrict__ mask) {
    __shared__ unsigned sh[NBIN];
    int tid = threadIdx.x, lane = tid & 31;
    ((uint4*)sh)[tid] = make_uint4(0, 0, 0, 0);
    __syncthreads();

    int s = blockIdx.y;
    int cpos = 0, cnz = 0;
    #pragma unroll
    for (int it = 0; it < 2; it++) {
        int e = blockIdx.x * 512 + it * 256 + tid;
        int i = e * 4;
        const float4 x = *(const float4*)(preds + (size_t)(s * NCH + 6) * PIX + i);
        const int4   m = *(const int4*)(mask + (size_t)s * PIX + i);
        float pn[4];
        pn[0] = sigmoidf(x.x) * (float)m.x;
        pn[1] = sigmoidf(x.y) * (float)m.y;
        pn[2] = sigmoidf(x.z) * (float)m.z;
        pn[3] = sigmoidf(x.w) * (float)m.w;
        *(float4*)(g_predn + (size_t)s * PIX + i) = make_float4(pn[0], pn[1], pn[2], pn[3]);
        unsigned wb[4];
        #pragma unroll
        for (int j = 0; j < 4; j++) {
            bool ispos = pn[j] >= 0.5f;
            cpos += ispos;
            cnz  += (!ispos) && (pn[j] > 0.f);
            wb[j] = __ballot_sync(0xffffffffu, ispos);
            hist_add(sh, !ispos, __float_as_uint(pn[j]) >> 20);
        }
        if (lane == 0)
            g_wbits[s * NCHUNK + (e >> 5)] = make_uint4(wb[0], wb[1], wb[2], wb[3]);
    }
    #pragma unroll
    for (int o = 16; o; o >>= 1) {
        cpos += __shfl_down_sync(0xffffffffu, cpos, o);
        cnz  += __shfl_down_sync(0xffffffffu, cnz, o);
    }
    if (lane == 0) {
        if (cpos) atomicAdd(&g_npos[s], cpos);
        if (cnz)  atomicAdd(&g_nzneg[s], cnz);
    }
    __syncthreads();
    #pragma unroll
    for (int b = tid; b < NBIN; b += 256) {
        unsigned c = sh[b];
        if (c) atomicAdd(&g_histA[s][b], c);
    }
}

// ---------------- radix pass 1 ----------------
__global__ void k_hist1() {
    int s = blockIdx.y;
    unsigned k;
    if (!needs_radix(s, k)) return;
    __shared__ unsigned sh[NBIN];
    __shared__ unsigned shbuf[10];
    int tid = threadIdx.x;
    ((uint4*)sh)[tid] = make_uint4(0, 0, 0, 0);
    unsigned d0, krem0;
    radix_pick(g_histA[s], k, shbuf, d0, krem0);
    if (blockIdx.x == 0 && tid == 0) { g_d0[s] = d0; g_krem0[s] = krem0; }
    #pragma unroll
    for (int it = 0; it < 2; it++) {
        int i = (blockIdx.x * 512 + it * 256 + tid) * 4;
        float4 v = *(const float4*)(g_predn + (size_t)s * PIX + i);
        float vv[4] = {v.x, v.y, v.z, v.w};
        #pragma unroll
        for (int j = 0; j < 4; j++) {
            unsigned b = __float_as_uint(vv[j]);
            bool hit = (vv[j] < 0.5f) && ((b >> 20) == d0);
            hist_add(sh, hit, (b >> 10) & (NBIN - 1u));
        }
    }
    __syncthreads();
    #pragma unroll
    for (int b = tid; b < NBIN; b += 256) {
        unsigned c = sh[b];
        if (c) atomicAdd(&g_histB[s][b], c);
    }
}

// ---------------- radix pass 2 ----------------
__global__ void k_hist2() {
    int s = blockIdx.y;
    unsigned k;
    if (!needs_radix(s, k)) return;
    __shared__ unsigned sh[NBIN];
    __shared__ unsigned shbuf[10];
    int tid = threadIdx.x;
    ((uint4*)sh)[tid] = make_uint4(0, 0, 0, 0);
    unsigned d1, krem1;
    radix_pick(g_histB[s], g_krem0[s], shbuf, d1, krem1);
    unsigned pref1 = (g_d0[s] << 10) | d1;
    if (blockIdx.x == 0 && tid == 0) { g_pref1[s] = pref1; g_krem1[s] = krem1; }
    #pragma unroll
    for (int it = 0; it < 2; it++) {
        int i = (blockIdx.x * 512 + it * 256 + tid) * 4;
        float4 v = *(const float4*)(g_predn + (size_t)s * PIX + i);
        float vv[4] = {v.x, v.y, v.z, v.w};
        #pragma unroll
        for (int j = 0; j < 4; j++) {
            unsigned b = __float_as_uint(vv[j]);
            bool hit = (vv[j] < 0.5f) && ((b >> 10) == pref1);
            hist_add(sh, hit, b & (NBIN - 1u));
        }
    }
    __syncthreads();
    #pragma unroll
    for (int b = tid; b < NBIN; b += 256) {
        unsigned c = sh[b];
        if (c) atomicAdd(&g_histC[s][b], c);
    }
}

// ---------------- Ls reduce: TMA pipeline over pred[s,c] + label[s,c] ------
__global__ void __launch_bounds__(256) k_reduce_ls(const float* __restrict__ preds,
                                                   const int* __restrict__ labels) {
    extern __shared__ char dsm[];
    __shared__ float shred[8][3];
    uint32_t mbar0 = smem_u32(dsm);          // 4 barriers, 8B each
    char* stages = dsm + 128;
    int tid = threadIdx.x, lane = tid & 31, warp = tid >> 5;
    int s = blockIdx.y, c = blockIdx.z;
    const float* pbase = preds + (size_t)(s * NCH + c) * PIX;
    const int*   lbase = labels + (size_t)(s * NCH + c) * PIX;
    const uint4* wbase = g_wbits + s * NCHUNK;

    if (tid == 0) {
        #pragma unroll
        for (int i = 0; i < NSTAGE; i++) mbar_init(mbar0 + 8 * i, 1);
        asm volatile("fence.proxy.async.shared::cta;" ::: "memory");
    }
    __syncthreads();

    int t0 = blockIdx.x;
    if (tid == 0) {   // prologue: fill up to NSTAGE stages
        int kk = 0;
        for (int t = t0; t < NTILES && kk < NSTAGE; t += LS_GRIDX, kk++) {
            uint32_t sb = smem_u32(stages + kk * LS_STAGE_BYTES);
            mbar_expect_tx(mbar0 + 8 * kk, LS_STAGE_BYTES);
            bulk_g2s(sb, pbase + t * TILE_PX, TILE_PX * 4, mbar0 + 8 * kk);
            bulk_g2s(sb + TILE_PX * 4, lbase + t * TILE_PX, TILE_PX * 4, mbar0 + 8 * kk);
        }
    }

    float a0 = 0.f, a1 = 0.f, a2 = 0.f;
    int it = 0;
    for (int t = t0; t < NTILES; t += LS_GRIDX, it++) {
        int slot = it & (NSTAGE - 1);
        mbar_wait(mbar0 + 8 * slot, (it >> 2) & 1);
        const float4* sp = (const float4*)(stages + slot * LS_STAGE_BYTES);
        const int4*   sl = (const int4*)(stages + slot * LS_STAGE_BYTES + TILE_PX * 4);
        uint4 W4 = wbase[(t * TILE_PX + tid * 8) >> 7];
        unsigned wsh = (unsigned)((tid * 2) & 31);
        #pragma unroll
        for (int r = 0; r < 2; r++) {
            float4 p4 = sp[tid * 2 + r];
            int4   l4 = sl[tid * 2 + r];
            float pv[4] = {p4.x, p4.y, p4.z, p4.w};
            int   lv[4] = {l4.x, l4.y, l4.z, l4.w};
            unsigned wcomp[4] = {W4.x, W4.y, W4.z, W4.w};
            #pragma unroll
            for (int j = 0; j < 4; j++) {
                float w  = (float)((wcomp[j] >> (wsh + r)) & 1u);
                float pc = sigmoidf(pv[j]) * w;
                float lf = (float)lv[j] * w;
                a0 += pc * lf;
                a1 += pc * pc;
                a2 += lf;
            }
        }
        __syncthreads();   // all threads done with this slot
        if (tid == 0) {
            int tn = t + LS_GRIDX * NSTAGE;
            if (tn < NTILES) {
                uint32_t sb = smem_u32(stages + slot * LS_STAGE_BYTES);
                mbar_expect_tx(mbar0 + 8 * slot, LS_STAGE_BYTES);
                bulk_g2s(sb, pbase + tn * TILE_PX, TILE_PX * 4, mbar0 + 8 * slot);
                bulk_g2s(sb + TILE_PX * 4, lbase + tn * TILE_PX, TILE_PX * 4, mbar0 + 8 * slot);
            }
        }
    }

    #pragma unroll
    for (int o = 16; o; o >>= 1) {
        a0 += __shfl_down_sync(0xffffffffu, a0, o);
        a1 += __shfl_down_sync(0xffffffffu, a1, o);
        a2 += __shfl_down_sync(0xffffffffu, a2, o);
    }
    if (lane == 0) { shred[warp][0] = a0; shred[warp][1] = a1; shred[warp][2] = a2; }
    __syncthreads();
    if (tid < 3) {
        float v = 0.f;
        #pragma unroll
        for (int w = 0; w < 8; w++) v += shred[w][tid];
        atomicAdd(&g_acc[s][3 + 3 * c + tid], v);
    }
}

// ---------------- Lc reduce: TMA pipeline over predn + label6 + mask + final
__global__ void __launch_bounds__(256) k_reduce_lc(const int* __restrict__ labels,
                                                   const int* __restrict__ mask,
                                                   float* __restrict__ out) {
    extern __shared__ char dsm[];
    __shared__ unsigned shbuf[10];
    __shared__ float shred[8][3];
    __shared__ bool  is_last;
    uint32_t mbar0 = smem_u32(dsm);
    char* stages = dsm + 128;
    int tid = threadIdx.x, lane = tid & 31, warp = tid >> 5;
    int s = blockIdx.y;
    const float* pnb   = g_predn + (size_t)s * PIX;
    const int*   lbase = labels + (size_t)(s * NCH + 6) * PIX;
    const int*   mbase = mask + (size_t)s * PIX;

    unsigned k;
    bool needThr = needs_radix(s, k);
    float thr = 0.f;
    if (needThr) {
        unsigned d2, dummy;
        radix_pick(g_histC[s], g_krem1[s], shbuf, d2, dummy);
        thr = __uint_as_float((g_pref1[s] << 10) | d2);   // exact 30-bit key
    }

    if (tid == 0) {
        #pragma unroll
        for (int i = 0; i < NSTAGE; i++) mbar_init(mbar0 + 8 * i, 1);
        asm volatile("fence.proxy.async.shared::cta;" ::: "memory");
    }
    __syncthreads();

    int t0 = blockIdx.x;
    if (tid == 0) {
        int kk = 0;
        for (int t = t0; t < NTILES && kk < NSTAGE; t += LC_GRIDX, kk++) {
            uint32_t sb = smem_u32(stages + kk * LC_STAGE_BYTES);
            mbar_expect_tx(mbar0 + 8 * kk, LC_STAGE_BYTES);
            bulk_g2s(sb,                 pnb + t * TILE_PX, TILE_PX * 4, mbar0 + 8 * kk);
            bulk_g2s(sb + TILE_PX * 4,   lbase + t * TILE_PX, TILE_PX * 4, mbar0 + 8 * kk);
            bulk_g2s(sb + TILE_PX * 8,   mbase + t * TILE_PX, TILE_PX * 4, mbar0 + 8 * kk);
        }
    }

    float a0 = 0.f, a1 = 0.f, a2 = 0.f;
    int it = 0;
    for (int t = t0; t < NTILES; t += LC_GRIDX, it++) {
        int slot = it & (NSTAGE - 1);
        mbar_wait(mbar0 + 8 * slot, (it >> 2) & 1);
        const float4* sp = (const float4*)(stages + slot * LC_STAGE_BYTES);
        const int4*   sl = (const int4*)(stages + slot * LC_STAGE_BYTES + TILE_PX * 4);
        const int4*   sm = (const int4*)(stages + slot * LC_STAGE_BYTES + TILE_PX * 8);
        #pragma unroll
        for (int r = 0; r < 2; r++) {
            float4 p4 = sp[tid * 2 + r];
            int4   l4 = sl[tid * 2 + r];
            int4   m4 = sm[tid * 2 + r];
            float pv[4] = {p4.x, p4.y, p4.z, p4.w};
            int   lv[4] = {l4.x, l4.y, l4.z, l4.w};
            int   mv[4] = {m4.x, m4.y, m4.z, m4.w};
            #pragma unroll
            for (int j = 0; j < 4; j++) {
                float M  = needThr ? (pv[j] >= thr ? 1.f : 0.f) : 1.f;
                float ln = (float)(lv[j] * mv[j]) * M;
                float pm = pv[j] * M;
                a0 += pm * ln;
                a1 += pm * pv[j];
                a2 += ln;
            }
        }
        __syncthreads();
        if (tid == 0) {
            int tn = t + LC_GRIDX * NSTAGE;
            if (tn < NTILES) {
                uint32_t sb = smem_u32(stages + slot * LC_STAGE_BYTES);
                mbar_expect_tx(mbar0 + 8 * slot, LC_STAGE_BYTES);
                bulk_g2s(sb,               pnb + tn * TILE_PX, TILE_PX * 4, mbar0 + 8 * slot);
                bulk_g2s(sb + TILE_PX * 4, lbase + tn * TILE_PX, TILE_PX * 4, mbar0 + 8 * slot);
                bulk_g2s(sb + TILE_PX * 8, mbase + tn * TILE_PX, TILE_PX * 4, mbar0 + 8 * slot);
            }
        }
    }

    #pragma unroll
    for (int o = 16; o; o >>= 1) {
        a0 += __shfl_down_sync(0xffffffffu, a0, o);
        a1 += __shfl_down_sync(0xffffffffu, a1, o);
        a2 += __shfl_down_sync(0xffffffffu, a2, o);
    }
    if (lane == 0) { shred[warp][0] = a0; shred[warp][1] = a1; shred[warp][2] = a2; }
    __syncthreads();
    if (tid < 3) {
        float v = 0.f;
        #pragma unroll
        for (int w = 0; w < 8; w++) v += shred[w][tid];
        atomicAdd(&g_acc[s][tid], v);
    }

    __threadfence();
    if (tid == 0)
        is_last = (atomicAdd(&g_counter, 1u) == (unsigned)(LC_GRIDX * S) - 1u);
    __syncthreads();
    if (is_last) {
        for (int b = tid; b < S * NBIN; b += 256) {
            ((unsigned*)g_histA)[b] = 0u;
            ((unsigned*)g_histB)[b] = 0u;
            ((unsigned*)g_histC)[b] = 0u;
        }
        if (tid < S) { g_npos[tid] = 0; g_nzneg[tid] = 0; }
        if (tid == 0) {
            float Lc_s = 0.f, Ls_s = 0.f, loss_s = 0.f;
            for (int ss = 0; ss < S; ss++) {
                float a[21];
                for (int t = 0; t < 21; t++) {
                    a[t] = __ldcg(&g_acc[ss][t]);
                    g_acc[ss][t] = 0.f;
                }
                float Lc = 1.f - (2.f * a[0]) / (a[1] + a[2] + EPSV);
                float d = 0.f;
                for (int cc = 0; cc < 6; cc++)
                    d += (2.f * a[3 + 3 * cc]) / (a[4 + 3 * cc] + a[5 + 3 * cc] + EPSV);
                float Ls = 1.f - d / 6.f;
                Lc_s += Lc; Ls_s += Ls;
                loss_s += LAMBDA * Lc + (1.f - LAMBDA) * Ls;
            }
            out[0] = Lc_s / (float)S;
            out[1] = Ls_s / (float)S;
            out[2] = loss_s / (float)S;
            g_counter = 0u;
        }
    }
}

// ---------------- launch ----------------
extern "C" void kernel_launch(void* const* d_in, const int* in_sizes, int n_in,
                              void* d_out, int out_size) {
    const float* preds  = (const float*)d_in[0];
    const int*   labels = (const int*)d_in[1];
    const int*   mask   = (const int*)d_in[2];
    float* out = (float*)d_out;

    cudaFuncSetAttribute(k_reduce_ls, cudaFuncAttributeMaxDynamicSharedMemorySize, LS_SMEM);
    cudaFuncSetAttribute(k_reduce_lc, cudaFuncAttributeMaxDynamicSharedMemorySize, LC_SMEM);

    k_predn<<<dim3(200, S), 256>>>(preds, mask);
    k_hist1<<<dim3(200, S), 256>>>();      // no-op when radix shortcut hits
    k_hist2<<<dim3(200, S), 256>>>();
    k_reduce_ls<<<dim3(LS_GRIDX, S, 6), 256, LS_SMEM>>>(preds, labels);
    k_reduce_lc<<<dim3(LC_GRIDX, S), 256, LC_SMEM>>>(labels, mask, out);
    (void)in_sizes; (void)n_in; (void)out_size;
}